// round 2
// baseline (speedup 1.0000x reference)
#include <cuda_runtime.h>
#include <cuda_bf16.h>
#include <cstdint>

#define D 128
#define TILE_ROWS 32
#define MLP_THREADS 256

typedef unsigned long long ull;

// -------- scratch buffers (no cudaMalloc allowed) --------
#define MAX_NODES 100000
__device__ float g_acc[(size_t)MAX_NODES * D];
__device__ float g_xA[(size_t)MAX_NODES * D];
__device__ float g_xB[(size_t)MAX_NODES * D];

// -------- packed fp32x2 helpers (Blackwell FFMA2) --------
__device__ __forceinline__ ull pack2(float lo, float hi) {
    ull r; asm("mov.b64 %0, {%1,%2};" : "=l"(r) : "f"(lo), "f"(hi)); return r;
}
__device__ __forceinline__ void fma2(ull &d, ull a, ull b) {
    asm("fma.rn.f32x2 %0, %1, %2, %0;" : "+l"(d) : "l"(a), "l"(b));
}
__device__ __forceinline__ float2 unpack2(ull v) {
    float2 f; asm("mov.b64 {%0,%1}, %2;" : "=f"(f.x), "=f"(f.y) : "l"(v)); return f;
}

// -------- acc = x (copy) --------
__global__ void copy_kernel(float4* __restrict__ dst, const float4* __restrict__ src, int n4) {
    int i = blockIdx.x * blockDim.x + threadIdx.x;
    if (i < n4) dst[i] = src[i];
}

// -------- scatter-add: acc[dst] += x[src], one warp per edge --------
__global__ void scatter_kernel(float* __restrict__ acc, const float* __restrict__ x,
                               const int* __restrict__ ei, int E) {
    int warp = (blockIdx.x * blockDim.x + threadIdx.x) >> 5;
    int lane = threadIdx.x & 31;
    if (warp >= E) return;
    int src = 0, dst = 0;
    if (lane == 0) {
        src = ei[warp];
        dst = ei[(size_t)E + warp];
    }
    src = __shfl_sync(0xffffffffu, src, 0);
    dst = __shfl_sync(0xffffffffu, dst, 0);
    float4 v = __ldg(((const float4*)x) + (size_t)src * 32 + lane);
    float* p = acc + (size_t)dst * D + lane * 4;
    asm volatile("red.global.add.v4.f32 [%0], {%1,%2,%3,%4};"
                 :: "l"(p), "f"(v.x), "f"(v.y), "f"(v.z), "f"(v.w)
                 : "memory");
}

// -------- fused GIN MLP: xout = relu(acc@W1 + b1)@W2 + b2 --------
__global__ void __launch_bounds__(MLP_THREADS, 1) mlp_kernel(
    const float* __restrict__ acc,
    const float* __restrict__ W1, const float* __restrict__ b1,
    const float* __restrict__ W2, const float* __restrict__ b2,
    float* __restrict__ xout, int n)
{
    extern __shared__ float smem[];
    float* W1s  = smem;                 // 16384 floats
    float* W2s  = W1s + 16384;          // 16384
    float* b1s  = W2s + 16384;          // 128
    float* b2s  = b1s + 128;            // 128
    float* rows = b2s + 128;            // 32*128 = 4096
    float* hs   = rows + 4096;          // 4096

    const int tid = threadIdx.x;

    // stage weights + biases
    {
        const float4* w1g = (const float4*)W1;
        const float4* w2g = (const float4*)W2;
        float4* w1s = (float4*)W1s;
        float4* w2s = (float4*)W2s;
        for (int i = tid; i < 4096; i += MLP_THREADS) { w1s[i] = w1g[i]; w2s[i] = w2g[i]; }
        if (tid < 128) { b1s[tid] = b1[tid]; b2s[tid] = b2[tid]; }
    }
    __syncthreads();

    const int cg = tid & 31;   // column group: cols 4*cg .. 4*cg+3
    const int rw = tid >> 5;   // row worker: rows 4*rw .. 4*rw+3 within tile

    const ull bp10 = pack2(b1s[cg * 4 + 0], b1s[cg * 4 + 1]);
    const ull bp11 = pack2(b1s[cg * 4 + 2], b1s[cg * 4 + 3]);
    const ull bp20 = pack2(b2s[cg * 4 + 0], b2s[cg * 4 + 1]);
    const ull bp21 = pack2(b2s[cg * 4 + 2], b2s[cg * 4 + 3]);

    const int ntiles = (n + TILE_ROWS - 1) / TILE_ROWS;
    for (int t = blockIdx.x; t < ntiles; t += gridDim.x) {
        const int row0 = t * TILE_ROWS;

        // load 32 rows x 128 cols of acc into SMEM
        for (int i = tid; i < 32 * 32; i += MLP_THREADS) {
            int r = i >> 5, c = i & 31;
            int row = row0 + r;
            float4 v = make_float4(0.f, 0.f, 0.f, 0.f);
            if (row < n) v = ((const float4*)acc)[(size_t)row * 32 + c];
            ((float4*)rows)[i] = v;
        }
        __syncthreads();

        // GEMM1: hs = relu(rows @ W1 + b1)
        {
            ull a00 = bp10, a01 = bp11, a10 = bp10, a11 = bp11;
            ull a20 = bp10, a21 = bp11, a30 = bp10, a31 = bp11;
            const float* r0 = rows + (rw * 4 + 0) * D;
            const float* r1 = rows + (rw * 4 + 1) * D;
            const float* r2 = rows + (rw * 4 + 2) * D;
            const float* r3 = rows + (rw * 4 + 3) * D;
            #pragma unroll 4
            for (int k = 0; k < D; k++) {
                ulonglong2 w = ((const ulonglong2*)(W1s + k * D))[cg];
                ull v0 = pack2(r0[k], r0[k]);
                ull v1 = pack2(r1[k], r1[k]);
                ull v2 = pack2(r2[k], r2[k]);
                ull v3 = pack2(r3[k], r3[k]);
                fma2(a00, w.x, v0); fma2(a01, w.y, v0);
                fma2(a10, w.x, v1); fma2(a11, w.y, v1);
                fma2(a20, w.x, v2); fma2(a21, w.y, v2);
                fma2(a30, w.x, v3); fma2(a31, w.y, v3);
            }
            #define STORE_H(RR, A0, A1) { \
                float2 p = unpack2(A0); float2 q = unpack2(A1); \
                float4 hv = make_float4(fmaxf(p.x, 0.f), fmaxf(p.y, 0.f), \
                                        fmaxf(q.x, 0.f), fmaxf(q.y, 0.f)); \
                ((float4*)(hs + (rw * 4 + (RR)) * D))[cg] = hv; }
            STORE_H(0, a00, a01)
            STORE_H(1, a10, a11)
            STORE_H(2, a20, a21)
            STORE_H(3, a30, a31)
            #undef STORE_H
        }
        __syncthreads();

        // GEMM2: xout = hs @ W2 + b2
        {
            ull a00 = bp20, a01 = bp21, a10 = bp20, a11 = bp21;
            ull a20 = bp20, a21 = bp21, a30 = bp20, a31 = bp21;
            const float* r0 = hs + (rw * 4 + 0) * D;
            const float* r1 = hs + (rw * 4 + 1) * D;
            const float* r2 = hs + (rw * 4 + 2) * D;
            const float* r3 = hs + (rw * 4 + 3) * D;
            #pragma unroll 4
            for (int k = 0; k < D; k++) {
                ulonglong2 w = ((const ulonglong2*)(W2s + k * D))[cg];
                ull v0 = pack2(r0[k], r0[k]);
                ull v1 = pack2(r1[k], r1[k]);
                ull v2 = pack2(r2[k], r2[k]);
                ull v3 = pack2(r3[k], r3[k]);
                fma2(a00, w.x, v0); fma2(a01, w.y, v0);
                fma2(a10, w.x, v1); fma2(a11, w.y, v1);
                fma2(a20, w.x, v2); fma2(a21, w.y, v2);
                fma2(a30, w.x, v3); fma2(a31, w.y, v3);
            }
            #define STORE_O(RR, A0, A1) { \
                int row = row0 + rw * 4 + (RR); \
                if (row < n) { \
                    float2 p = unpack2(A0); float2 q = unpack2(A1); \
                    ((float4*)(xout + (size_t)row * D))[cg] = make_float4(p.x, p.y, q.x, q.y); \
                } }
            STORE_O(0, a00, a01)
            STORE_O(1, a10, a11)
            STORE_O(2, a20, a21)
            STORE_O(3, a30, a31)
            #undef STORE_O
        }
        __syncthreads();
    }
}

// -------- readout: per-graph sum (batch is sorted -> contiguous segments) --------
__device__ __forceinline__ int lower_bound_i(const int* __restrict__ a, int lo, int hi, int v) {
    while (lo < hi) {
        int m = (lo + hi) >> 1;
        if (a[m] < v) lo = m + 1; else hi = m;
    }
    return lo;
}

__global__ void readout_kernel(float* __restrict__ out, const float* __restrict__ xf,
                               const int* __restrict__ batch, int n) {
    const int g = blockIdx.x;
    const int j = threadIdx.x;
    int lo = lower_bound_i(batch, 0, n, g);
    int hi = lower_bound_i(batch, lo, n, g + 1);
    float s0 = 0.f, s1 = 0.f, s2 = 0.f, s3 = 0.f;
    int r = lo;
    for (; r + 4 <= hi; r += 4) {
        s0 += xf[(size_t)(r + 0) * D + j];
        s1 += xf[(size_t)(r + 1) * D + j];
        s2 += xf[(size_t)(r + 2) * D + j];
        s3 += xf[(size_t)(r + 3) * D + j];
    }
    for (; r < hi; r++) s0 += xf[(size_t)r * D + j];
    out[(size_t)g * D + j] = (s0 + s1) + (s2 + s3);
}

// -------- launch --------
extern "C" void kernel_launch(void* const* d_in, const int* in_sizes, int n_in,
                              void* d_out, int out_size) {
    const float* x   = (const float*)d_in[0];
    const float* W1  = (const float*)d_in[1];
    const float* b1  = (const float*)d_in[2];
    const float* W2  = (const float*)d_in[3];
    const float* b2  = (const float*)d_in[4];
    const int* ei    = (const int*)d_in[5];   // int32 (JAX x64 disabled)
    const int* bat   = (const int*)d_in[6];   // int32
    float* out       = (float*)d_out;

    const int N = in_sizes[0] / D;               // 100000
    const int E = in_sizes[5] / 2;               // 1600000
    const int n_layers = in_sizes[1] / (D * D);  // 3

    float *acc, *xA, *xB;
    cudaGetSymbolAddress((void**)&acc, g_acc);
    cudaGetSymbolAddress((void**)&xA, g_xA);
    cudaGetSymbolAddress((void**)&xB, g_xB);

    const int smem_bytes = (16384 * 2 + 128 * 2 + 4096 * 2) * 4;  // 164864
    cudaFuncSetAttribute(mlp_kernel, cudaFuncAttributeMaxDynamicSharedMemorySize, smem_bytes);

    const int n4 = N * D / 4;
    const int copy_blocks = (n4 + 255) / 256;
    const int scat_blocks = (E + 7) / 8;   // 8 warps per block, 1 edge/warp

    const float* xin = x;
    float* bufs[2] = { xA, xB };

    for (int l = 0; l < n_layers; l++) {
        copy_kernel<<<copy_blocks, 256>>>((float4*)acc, (const float4*)xin, n4);
        scatter_kernel<<<scat_blocks, 256>>>(acc, xin, ei, E);
        mlp_kernel<<<148, MLP_THREADS, smem_bytes>>>(
            acc,
            W1 + (size_t)l * D * D, b1 + (size_t)l * D,
            W2 + (size_t)l * D * D, b2 + (size_t)l * D,
            bufs[l & 1], N);
        xin = bufs[l & 1];
    }

    readout_kernel<<<128, D>>>(out, xin, bat, N);
}

// round 3
// speedup vs baseline: 1.2696x; 1.2696x over previous
#include <cuda_runtime.h>
#include <cuda_bf16.h>
#include <cstdint>

#define D 128
#define TILE_ROWS 32
#define MLP_THREADS 256
#define SCAN_BLOCK 1024

typedef unsigned long long ull;

// -------- scratch buffers (no cudaMalloc allowed) --------
#define MAX_NODES 100000
#define MAX_EDGES 1600000
__device__ float g_acc[(size_t)MAX_NODES * D];
__device__ float g_xA[(size_t)MAX_NODES * D];
__device__ float g_xB[(size_t)MAX_NODES * D];
__device__ int   g_counts[MAX_NODES];
__device__ int   g_partial[MAX_NODES];
__device__ int   g_offs[MAX_NODES + 1];
__device__ int   g_cursor[MAX_NODES];
__device__ int   g_bsum[256];
__device__ int   g_csr_src[MAX_EDGES];

// -------- packed fp32x2 helpers (Blackwell FFMA2) --------
__device__ __forceinline__ ull pack2(float lo, float hi) {
    ull r; asm("mov.b64 %0, {%1,%2};" : "=l"(r) : "f"(lo), "f"(hi)); return r;
}
__device__ __forceinline__ void fma2(ull &d, ull a, ull b) {
    asm("fma.rn.f32x2 %0, %1, %2, %0;" : "+l"(d) : "l"(a), "l"(b));
}
__device__ __forceinline__ float2 unpack2(ull v) {
    float2 f; asm("mov.b64 {%0,%1}, %2;" : "=f"(f.x), "=f"(f.y) : "l"(v)); return f;
}

// ================= CSR build =================
__global__ void zero_kernel(int* __restrict__ p, int n) {
    int i = blockIdx.x * blockDim.x + threadIdx.x;
    if (i < n) p[i] = 0;
}

__global__ void hist_kernel(const int* __restrict__ ei, int E, int* __restrict__ counts) {
    int e = blockIdx.x * blockDim.x + threadIdx.x;
    if (e < E) atomicAdd(&counts[ei[(size_t)E + e]], 1);
}

__global__ void scan_part_kernel(const int* __restrict__ counts, int N,
                                 int* __restrict__ partial, int* __restrict__ bsum) {
    __shared__ int sm[SCAN_BLOCK];
    int i = blockIdx.x * SCAN_BLOCK + threadIdx.x;
    int v = (i < N) ? counts[i] : 0;
    sm[threadIdx.x] = v;
    __syncthreads();
    for (int off = 1; off < SCAN_BLOCK; off <<= 1) {
        int t = (threadIdx.x >= off) ? sm[threadIdx.x - off] : 0;
        __syncthreads();
        sm[threadIdx.x] += t;
        __syncthreads();
    }
    if (i < N) partial[i] = sm[threadIdx.x];          // inclusive within block
    if (threadIdx.x == SCAN_BLOCK - 1) bsum[blockIdx.x] = sm[threadIdx.x];
}

__global__ void scan_bsum_kernel(int* __restrict__ bsum, int nb) {
    if (threadIdx.x == 0) {
        int s = 0;
        for (int i = 0; i < nb; i++) { int t = bsum[i]; bsum[i] = s; s += t; }
    }
}

__global__ void scan_final_kernel(const int* __restrict__ partial, const int* __restrict__ counts,
                                  const int* __restrict__ bsum, int N, int E,
                                  int* __restrict__ offs, int* __restrict__ cursor) {
    int i = blockIdx.x * SCAN_BLOCK + threadIdx.x;
    if (i < N) {
        int v = partial[i] - counts[i] + bsum[blockIdx.x];  // exclusive prefix
        offs[i] = v;
        cursor[i] = v;
    }
    if (i == 0) offs[N] = E;
}

__global__ void fill_kernel(const int* __restrict__ ei, int E,
                            int* __restrict__ cursor, int* __restrict__ csr_src) {
    int e = blockIdx.x * blockDim.x + threadIdx.x;
    if (e < E) {
        int d = ei[(size_t)E + e];
        int pos = atomicAdd(&cursor[d], 1);
        csr_src[pos] = ei[e];
    }
}

// ================= gather: acc[v] = x[v] + sum_{u in in(v)} x[u] =================
__global__ void gather_kernel(float4* __restrict__ acc, const float4* __restrict__ x,
                              const int* __restrict__ offs, const int* __restrict__ csr,
                              int N) {
    int warp = (blockIdx.x * blockDim.x + threadIdx.x) >> 5;
    int lane = threadIdx.x & 31;
    if (warp >= N) return;
    int lo = offs[warp];
    int hi = offs[warp + 1];
    float4 a = x[(size_t)warp * 32 + lane];
    for (int base = lo; base < hi; base += 32) {
        int cnt = hi - base; if (cnt > 32) cnt = 32;
        int idx = (lane < cnt) ? csr[base + lane] : 0;
        #pragma unroll 4
        for (int j = 0; j < cnt; j++) {
            int s = __shfl_sync(0xffffffffu, idx, j);
            float4 v = __ldg(x + (size_t)s * 32 + lane);
            a.x += v.x; a.y += v.y; a.z += v.z; a.w += v.w;
        }
    }
    acc[(size_t)warp * 32 + lane] = a;
}

// ================= fused GIN MLP: xout = relu(acc@W1 + b1)@W2 + b2 =================
// rows/hs are stored DUPLICATED in SMEM ({v,v} 8-byte pairs) so the FFMA2 inner
// loop needs no pack movs: one broadcast LDS.64 per row value.
__global__ void __launch_bounds__(MLP_THREADS, 1) mlp_kernel(
    const float* __restrict__ acc,
    const float* __restrict__ W1, const float* __restrict__ b1,
    const float* __restrict__ W2, const float* __restrict__ b2,
    float* __restrict__ xout, int n)
{
    extern __shared__ float smem[];
    float* W1s = smem;                  // 16384 floats
    float* W2s = W1s + 16384;           // 16384
    float* b1s = W2s + 16384;           // 128
    float* b2s = b1s + 128;             // 128
    float* rowsd = b2s + 128;           // 32 * 256 = 8192 (dup pairs)
    float* hsd   = rowsd + 8192;        // 8192

    const int tid = threadIdx.x;

    {
        const float4* w1g = (const float4*)W1;
        const float4* w2g = (const float4*)W2;
        float4* w1s = (float4*)W1s;
        float4* w2s = (float4*)W2s;
        for (int i = tid; i < 4096; i += MLP_THREADS) { w1s[i] = w1g[i]; w2s[i] = w2g[i]; }
        if (tid < 128) { b1s[tid] = b1[tid]; b2s[tid] = b2[tid]; }
    }
    __syncthreads();

    const int cg = tid & 31;   // column group: cols 4*cg .. 4*cg+3
    const int rw = tid >> 5;   // row worker: rows 4*rw .. 4*rw+3 within tile

    const ull bp10 = pack2(b1s[cg * 4 + 0], b1s[cg * 4 + 1]);
    const ull bp11 = pack2(b1s[cg * 4 + 2], b1s[cg * 4 + 3]);
    const ull bp20 = pack2(b2s[cg * 4 + 0], b2s[cg * 4 + 1]);
    const ull bp21 = pack2(b2s[cg * 4 + 2], b2s[cg * 4 + 3]);

    const int ntiles = (n + TILE_ROWS - 1) / TILE_ROWS;
    for (int t = blockIdx.x; t < ntiles; t += gridDim.x) {
        const int row0 = t * TILE_ROWS;

        // load 32 rows x 128 cols of acc into SMEM, duplicated
        for (int i = tid; i < 32 * 32; i += MLP_THREADS) {
            int r = i >> 5, c = i & 31;
            int row = row0 + r;
            float4 v = make_float4(0.f, 0.f, 0.f, 0.f);
            if (row < n) v = ((const float4*)acc)[(size_t)row * 32 + c];
            float4* dp = (float4*)(rowsd + (size_t)(r * 128 + c * 4) * 2);
            dp[0] = make_float4(v.x, v.x, v.y, v.y);
            dp[1] = make_float4(v.z, v.z, v.w, v.w);
        }
        __syncthreads();

        // GEMM1: hsd = dup(relu(rows @ W1 + b1))
        {
            ull a00 = bp10, a01 = bp11, a10 = bp10, a11 = bp11;
            ull a20 = bp10, a21 = bp11, a30 = bp10, a31 = bp11;
            const float* r0 = rowsd + (rw * 4 + 0) * 256;
            const float* r1 = rowsd + (rw * 4 + 1) * 256;
            const float* r2 = rowsd + (rw * 4 + 2) * 256;
            const float* r3 = rowsd + (rw * 4 + 3) * 256;
            #pragma unroll 4
            for (int k = 0; k < D; k++) {
                ulonglong2 w = ((const ulonglong2*)(W1s + k * D))[cg];
                ull v0 = *(const ull*)(r0 + 2 * k);
                ull v1 = *(const ull*)(r1 + 2 * k);
                ull v2 = *(const ull*)(r2 + 2 * k);
                ull v3 = *(const ull*)(r3 + 2 * k);
                fma2(a00, w.x, v0); fma2(a01, w.y, v0);
                fma2(a10, w.x, v1); fma2(a11, w.y, v1);
                fma2(a20, w.x, v2); fma2(a21, w.y, v2);
                fma2(a30, w.x, v3); fma2(a31, w.y, v3);
            }
            #define STORE_H(RR, A0, A1) { \
                float2 p = unpack2(A0); float2 q = unpack2(A1); \
                float h0 = fmaxf(p.x, 0.f), h1 = fmaxf(p.y, 0.f); \
                float h2 = fmaxf(q.x, 0.f), h3 = fmaxf(q.y, 0.f); \
                float4* dp = (float4*)(hsd + (size_t)((rw * 4 + (RR)) * 128 + cg * 4) * 2); \
                dp[0] = make_float4(h0, h0, h1, h1); \
                dp[1] = make_float4(h2, h2, h3, h3); }
            STORE_H(0, a00, a01)
            STORE_H(1, a10, a11)
            STORE_H(2, a20, a21)
            STORE_H(3, a30, a31)
            #undef STORE_H
        }
        __syncthreads();

        // GEMM2: xout = hs @ W2 + b2
        {
            ull a00 = bp20, a01 = bp21, a10 = bp20, a11 = bp21;
            ull a20 = bp20, a21 = bp21, a30 = bp20, a31 = bp21;
            const float* r0 = hsd + (rw * 4 + 0) * 256;
            const float* r1 = hsd + (rw * 4 + 1) * 256;
            const float* r2 = hsd + (rw * 4 + 2) * 256;
            const float* r3 = hsd + (rw * 4 + 3) * 256;
            #pragma unroll 4
            for (int k = 0; k < D; k++) {
                ulonglong2 w = ((const ulonglong2*)(W2s + k * D))[cg];
                ull v0 = *(const ull*)(r0 + 2 * k);
                ull v1 = *(const ull*)(r1 + 2 * k);
                ull v2 = *(const ull*)(r2 + 2 * k);
                ull v3 = *(const ull*)(r3 + 2 * k);
                fma2(a00, w.x, v0); fma2(a01, w.y, v0);
                fma2(a10, w.x, v1); fma2(a11, w.y, v1);
                fma2(a20, w.x, v2); fma2(a21, w.y, v2);
                fma2(a30, w.x, v3); fma2(a31, w.y, v3);
            }
            #define STORE_O(RR, A0, A1) { \
                int row = row0 + rw * 4 + (RR); \
                if (row < n) { \
                    float2 p = unpack2(A0); float2 q = unpack2(A1); \
                    ((float4*)(xout + (size_t)row * D))[cg] = make_float4(p.x, p.y, q.x, q.y); \
                } }
            STORE_O(0, a00, a01)
            STORE_O(1, a10, a11)
            STORE_O(2, a20, a21)
            STORE_O(3, a30, a31)
            #undef STORE_O
        }
        __syncthreads();
    }
}

// ================= readout: per-graph sum (batch sorted -> contiguous) =================
__device__ __forceinline__ int lower_bound_i(const int* __restrict__ a, int lo, int hi, int v) {
    while (lo < hi) {
        int m = (lo + hi) >> 1;
        if (a[m] < v) lo = m + 1; else hi = m;
    }
    return lo;
}

__global__ void readout_kernel(float* __restrict__ out, const float* __restrict__ xf,
                               const int* __restrict__ batch, int n) {
    const int g = blockIdx.x;
    const int j = threadIdx.x;
    int lo = lower_bound_i(batch, 0, n, g);
    int hi = lower_bound_i(batch, lo, n, g + 1);
    float s0 = 0.f, s1 = 0.f, s2 = 0.f, s3 = 0.f;
    int r = lo;
    for (; r + 4 <= hi; r += 4) {
        s0 += xf[(size_t)(r + 0) * D + j];
        s1 += xf[(size_t)(r + 1) * D + j];
        s2 += xf[(size_t)(r + 2) * D + j];
        s3 += xf[(size_t)(r + 3) * D + j];
    }
    for (; r < hi; r++) s0 += xf[(size_t)r * D + j];
    out[(size_t)g * D + j] = (s0 + s1) + (s2 + s3);
}

// ================= launch =================
extern "C" void kernel_launch(void* const* d_in, const int* in_sizes, int n_in,
                              void* d_out, int out_size) {
    const float* x   = (const float*)d_in[0];
    const float* W1  = (const float*)d_in[1];
    const float* b1  = (const float*)d_in[2];
    const float* W2  = (const float*)d_in[3];
    const float* b2  = (const float*)d_in[4];
    const int* ei    = (const int*)d_in[5];   // int32
    const int* bat   = (const int*)d_in[6];   // int32
    float* out       = (float*)d_out;

    const int N = in_sizes[0] / D;               // 100000
    const int E = in_sizes[5] / 2;               // 1600000
    const int n_layers = in_sizes[1] / (D * D);  // 3

    float *acc, *xA, *xB;
    int *counts, *partial, *offs, *cursor, *bsum, *csr;
    cudaGetSymbolAddress((void**)&acc, g_acc);
    cudaGetSymbolAddress((void**)&xA, g_xA);
    cudaGetSymbolAddress((void**)&xB, g_xB);
    cudaGetSymbolAddress((void**)&counts, g_counts);
    cudaGetSymbolAddress((void**)&partial, g_partial);
    cudaGetSymbolAddress((void**)&offs, g_offs);
    cudaGetSymbolAddress((void**)&cursor, g_cursor);
    cudaGetSymbolAddress((void**)&bsum, g_bsum);
    cudaGetSymbolAddress((void**)&csr, g_csr_src);

    const int smem_bytes = (16384 * 2 + 128 * 2 + 8192 * 2) * 4;  // 198144
    cudaFuncSetAttribute(mlp_kernel, cudaFuncAttributeMaxDynamicSharedMemorySize, smem_bytes);

    // ---- CSR build (once per launch) ----
    const int nscan = (N + SCAN_BLOCK - 1) / SCAN_BLOCK;
    zero_kernel<<<(N + 255) / 256, 256>>>(counts, N);
    hist_kernel<<<(E + 255) / 256, 256>>>(ei, E, counts);
    scan_part_kernel<<<nscan, SCAN_BLOCK>>>(counts, N, partial, bsum);
    scan_bsum_kernel<<<1, 32>>>(bsum, nscan);
    scan_final_kernel<<<nscan, SCAN_BLOCK>>>(partial, counts, bsum, N, E, offs, cursor);
    fill_kernel<<<(E + 255) / 256, 256>>>(ei, E, cursor, csr);

    // ---- layers ----
    const int gather_blocks = (N * 32 + 255) / 256;  // warp per node
    const float* xin = x;
    float* bufs[2] = { xA, xB };

    for (int l = 0; l < n_layers; l++) {
        gather_kernel<<<gather_blocks, 256>>>((float4*)acc, (const float4*)xin, offs, csr, N);
        mlp_kernel<<<148, MLP_THREADS, smem_bytes>>>(
            acc,
            W1 + (size_t)l * D * D, b1 + (size_t)l * D,
            W2 + (size_t)l * D * D, b2 + (size_t)l * D,
            bufs[l & 1], N);
        xin = bufs[l & 1];
    }

    readout_kernel<<<128, D>>>(out, xin, bat, N);
}